// round 6
// baseline (speedup 1.0000x reference)
#include <cuda_runtime.h>
#include <cstdint>
#include <cstddef>

// Net_quantize: fused MFL recurrence + LSQ fake-quant + 2 quantized linear layers.
// One thread per row. x staged through SMEM in 256x16 chunks, double-buffered,
// with a swizzled layout making BOTH the staging STS.128 and the per-row LDS.128
// bank-conflict-free. fc1/fc2 via DP4A on exact int8 quantization levels.
//
// swizzle: element (row, q, b) (q = quad 0..3, b = 0..3) lives at
//          xs[row*16 + ((q + (row>>1)) & 3)*4 + b]

#define THREADS 256
#define NCOLS   128
#define NCHUNK  8             // 16 cols per chunk
#define XPAD    16
#define BUFSZ   (THREADS * XPAD)

__global__ __launch_bounds__(THREADS, 4)
void net_quant_kernel(const float* __restrict__ x,
                      const float* __restrict__ p_alpha,
                      const float* __restrict__ p_beta,
                      const float* __restrict__ p_a1,
                      const float* __restrict__ p_a2,
                      const float* __restrict__ p_a3,
                      const float* __restrict__ W1,
                      const float* __restrict__ b1,
                      const float* __restrict__ p_wa1,
                      const float* __restrict__ W2,
                      const float* __restrict__ b2,
                      const float* __restrict__ p_wa2,
                      float* __restrict__ out)
{
    __shared__ float xs[2 * BUFSZ];       // 32 KiB double-buffered staging
    __shared__ int   w1p[32 * 16];        // [kc][j], kc = k/4
    __shared__ int   w2p[10 * 4];         // [j][c]

    const int tid  = threadIdx.x;
    const int row0 = blockIdx.x * THREADS;

    const float alpha = p_alpha[0];
    const float beta  = p_beta[0];
    const float a1  = p_a1[0];
    const float a2  = p_a2[0];
    const float a3  = p_a3[0];
    const float wa1 = p_wa1[0];
    const float wa2 = p_wa2[0];
    const float inv_a1  = 1.0f / a1;
    const float inv_a2  = 1.0f / a2;
    const float inv_a3  = 1.0f / a3;
    const float inv_wa1 = 1.0f / wa1;
    const float inv_wa2 = 1.0f / wa2;

    // ---- quantize + pack W1 (16x128) into smem, layout [kc][j] ----
    for (int i = tid; i < 512; i += THREADS) {
        const int kc = i >> 4, j = i & 15;
        unsigned v = 0;
#pragma unroll
        for (int b = 0; b < 4; ++b) {
            float t = W1[j * 128 + kc * 4 + b] * inv_wa1;
            int q;
            asm("cvt.rni.sat.s8.f32 %0, %1;" : "=r"(q) : "f"(t));
            v = __byte_perm(v, (unsigned)q, 0x4321);
        }
        w1p[i] = (int)v;
    }
    // ---- quantize + pack W2 (10x16) ----
    if (tid < 40) {
        const int j = tid >> 2, c = tid & 3;
        unsigned v = 0;
#pragma unroll
        for (int b = 0; b < 4; ++b) {
            float t = W2[j * 16 + c * 4 + b] * inv_wa2;
            int q;
            asm("cvt.rni.sat.s8.f32 %0, %1;" : "=r"(q) : "f"(t));
            v = __byte_perm(v, (unsigned)v ? (unsigned)q : (unsigned)q, 0x4321);
        }
        w2p[tid] = (int)v;
    }
    // (w1p/w2p ordered for all threads by the first pipeline __syncthreads)

    // ---- pipelined staging + MFL recurrence + fc1 ----
    // staging: per chunk 256 rows x 4 quads of float4; thread handles quad
    // q0 = tid&3 of rows r_i = i*64 + (tid>>2), i = 0..3.
    const float4* x4 = reinterpret_cast<const float4*>(x) + (size_t)row0 * (NCOLS / 4);
    const int r0 = tid >> 2, q0 = tid & 3;

    float4 pf0, pf1, pf2, pf3;
    pf0 = x4[(size_t)r0 * 32 + q0];
    pf1 = x4[(size_t)(64 + r0) * 32 + q0];
    pf2 = x4[(size_t)(128 + r0) * 32 + q0];
    pf3 = x4[(size_t)(192 + r0) * 32 + q0];

    float w = 1.0f;
    int acc[16];
#pragma unroll
    for (int j = 0; j < 16; ++j) acc[j] = 0;
    unsigned hp = 0;

#pragma unroll
    for (int c = 0; c < NCHUNK; ++c) {
        float* buf = xs + (c & 1) * BUFSZ;

        // swizzled vector stores of prefetched chunk c (conflict-free STS.128)
        {
            const int rA = r0,       sA = (q0 + (rA >> 1)) & 3;
            const int rB = 64 + r0,  sB = (q0 + (rB >> 1)) & 3;
            const int rC = 128 + r0, sC = (q0 + (rC >> 1)) & 3;
            const int rD = 192 + r0, sD = (q0 + (rD >> 1)) & 3;
            *reinterpret_cast<float4*>(&buf[rA * XPAD + sA * 4]) = pf0;
            *reinterpret_cast<float4*>(&buf[rB * XPAD + sB * 4]) = pf1;
            *reinterpret_cast<float4*>(&buf[rC * XPAD + sC * 4]) = pf2;
            *reinterpret_cast<float4*>(&buf[rD * XPAD + sD * 4]) = pf3;
        }

        // issue LDGs for chunk c+1 before the barrier (latency under compute)
        if (c < NCHUNK - 1) {
            const size_t cb = (size_t)(c + 1) * 4 + q0;
            pf0 = x4[(size_t)r0 * 32 + cb];
            pf1 = x4[(size_t)(64 + r0) * 32 + cb];
            pf2 = x4[(size_t)(128 + r0) * 32 + cb];
            pf3 = x4[(size_t)(192 + r0) * 32 + cb];
        }

        __syncthreads();

        // 16 recurrence steps + 4 dp4a groups; one vector LDS per group
        const float* xr = &buf[tid * XPAD];
        const int half = tid >> 1;
#pragma unroll
        for (int g = 0; g < 4; ++g) {
            const int s = (g + half) & 3;
            const float4 v = *reinterpret_cast<const float4*>(&xr[s * 4]);
            const float xe[4] = {v.x, v.y, v.z, v.w};
#pragma unroll
            for (int b = 0; b < 4; ++b) {
                // quantize w_k: clip+round-half-even == cvt.rni.sat.s8
                const float t = w * inv_a1;
                int hq;
                asm("cvt.rni.sat.s8.f32 %0, %1;" : "=r"(hq) : "f"(t));
                hp = __byte_perm(hp, (unsigned)hq, 0x4321);
                // w' = alpha*rcp(w) + (w - beta*x_k); t2 fma overlaps the MUFU
                const float t2 = __fmaf_rn(-beta, xe[b], w);
                float r;
                asm("rcp.approx.f32 %0, %1;" : "=f"(r) : "f"(w));
                w = __fmaf_rn(alpha, r, t2);
            }
            const int kc = c * 4 + g;
            const int4* wp = reinterpret_cast<const int4*>(&w1p[kc * 16]);
            const int4 w0 = wp[0], w1v = wp[1], w2v = wp[2], w3v = wp[3];
            acc[0]  = __dp4a((int)hp, w0.x,  acc[0]);
            acc[1]  = __dp4a((int)hp, w0.y,  acc[1]);
            acc[2]  = __dp4a((int)hp, w0.z,  acc[2]);
            acc[3]  = __dp4a((int)hp, w0.w,  acc[3]);
            acc[4]  = __dp4a((int)hp, w1v.x, acc[4]);
            acc[5]  = __dp4a((int)hp, w1v.y, acc[5]);
            acc[6]  = __dp4a((int)hp, w1v.z, acc[6]);
            acc[7]  = __dp4a((int)hp, w1v.w, acc[7]);
            acc[8]  = __dp4a((int)hp, w2v.x, acc[8]);
            acc[9]  = __dp4a((int)hp, w2v.y, acc[9]);
            acc[10] = __dp4a((int)hp, w2v.z, acc[10]);
            acc[11] = __dp4a((int)hp, w2v.w, acc[11]);
            acc[12] = __dp4a((int)hp, w3v.x, acc[12]);
            acc[13] = __dp4a((int)hp, w3v.y, acc[13]);
            acc[14] = __dp4a((int)hp, w3v.z, acc[14]);
            acc[15] = __dp4a((int)hp, w3v.w, acc[15]);
        }
    }

    // ---- epilogue: bias, sigmoid, unsigned quant, signed quant, fc2 (dp4a) ----
    const float s1scale = a1 * wa1;
    unsigned sp[4];
    unsigned spacc = 0;
#pragma unroll
    for (int j = 0; j < 16; ++j) {
        const float h = __fmaf_rn((float)acc[j], s1scale, b1[j]);
        const float sg = __fdividef(1.0f, 1.0f + __expf(-h));
        float u = sg * inv_a2;
        u = fminf(fmaxf(u, 0.0f), 255.0f);
        const float s = (float)__float2int_rn(u) * a2;          // post-sigmoid fq
        const float v2 = s * inv_a3;
        int s2q;
        asm("cvt.rni.sat.s8.f32 %0, %1;" : "=r"(s2q) : "f"(v2)); // qAct3 level
        spacc = __byte_perm(spacc, (unsigned)s2q, 0x4321);
        if ((j & 3) == 3) sp[j >> 2] = spacc;
    }

    // buffer 0 is idle once chunk 6's compute finished (everyone passed sync 7)
    float* outs = xs;
    const float s2scale = a3 * wa2;
#pragma unroll
    for (int j = 0; j < 10; ++j) {
        int o = 0;
        o = __dp4a((int)sp[0], w2p[j * 4 + 0], o);
        o = __dp4a((int)sp[1], w2p[j * 4 + 1], o);
        o = __dp4a((int)sp[2], w2p[j * 4 + 2], o);
        o = __dp4a((int)sp[3], w2p[j * 4 + 3], o);
        outs[tid * 10 + j] = __fmaf_rn((float)o, s2scale, b2[j]);
    }
    __syncthreads();

    // coalesced output store: 2560 contiguous floats per block
    const size_t obase = (size_t)row0 * 10;
#pragma unroll
    for (int t = 0; t < 10; ++t) {
        const int i = t * THREADS + tid;
        out[obase + i] = outs[i];
    }
}

extern "C" void kernel_launch(void* const* d_in, const int* in_sizes, int n_in,
                              void* d_out, int out_size)
{
    const float* x       = (const float*)d_in[0];
    const float* p_alpha = (const float*)d_in[1];
    const float* p_beta  = (const float*)d_in[2];
    const float* p_a1    = (const float*)d_in[3];
    const float* p_a2    = (const float*)d_in[4];
    const float* p_a3    = (const float*)d_in[5];
    const float* W1      = (const float*)d_in[6];
    const float* b1      = (const float*)d_in[7];
    const float* p_wa1   = (const float*)d_in[8];
    const float* W2      = (const float*)d_in[9];
    const float* b2      = (const float*)d_in[10];
    const float* p_wa2   = (const float*)d_in[11];
    float* out = (float*)d_out;

    const int M = in_sizes[0] / NCOLS;     // 262144
    const int blocks = M / THREADS;        // 1024

    net_quant_kernel<<<blocks, THREADS>>>(x, p_alpha, p_beta, p_a1, p_a2, p_a3,
                                          W1, b1, p_wa1, W2, b2, p_wa2, out);
}

// round 7
// speedup vs baseline: 1.2097x; 1.2097x over previous
#include <cuda_runtime.h>
#include <cstdint>
#include <cstddef>

// Net_quantize: fused MFL recurrence + LSQ fake-quant + 2 quantized linear layers.
// One thread per row. x staged global->shared via cp.async.cg (no register
// footprint, L1-bypass), double-buffered, swizzled conflict-free layout.
// fc1/fc2 via DP4A on exact int8 quantization levels.
// launch_bounds(256,5) -> <=48 regs -> 5 CTAs/SM (62.5% occ).

#define THREADS 256
#define NCOLS   128
#define NCHUNK  8             // 16 cols per chunk
#define XPAD    16
#define BUFSZ   (THREADS * XPAD)

__device__ __forceinline__ void cp_async16(uint32_t saddr, const void* gptr) {
    asm volatile("cp.async.cg.shared.global [%0], [%1], 16;"
                 :: "r"(saddr), "l"(gptr) : "memory");
}
__device__ __forceinline__ void cp_commit() {
    asm volatile("cp.async.commit_group;" ::: "memory");
}
template <int N>
__device__ __forceinline__ void cp_wait() {
    asm volatile("cp.async.wait_group %0;" :: "n"(N) : "memory");
}

__global__ __launch_bounds__(THREADS, 5)
void net_quant_kernel(const float* __restrict__ x,
                      const float* __restrict__ p_alpha,
                      const float* __restrict__ p_beta,
                      const float* __restrict__ p_a1,
                      const float* __restrict__ p_a2,
                      const float* __restrict__ p_a3,
                      const float* __restrict__ W1,
                      const float* __restrict__ b1,
                      const float* __restrict__ p_wa1,
                      const float* __restrict__ W2,
                      const float* __restrict__ b2,
                      const float* __restrict__ p_wa2,
                      float* __restrict__ out)
{
    __shared__ float xs[2 * BUFSZ];       // 32 KiB double-buffered staging
    __shared__ int   w1p[32 * 16];        // [kc][j], kc = k/4
    __shared__ int   w2p[10 * 4];         // [j][c]
    __shared__ float b1s[16];
    __shared__ float b2s[10];

    const int tid  = threadIdx.x;
    const int row0 = blockIdx.x * THREADS;
    const int r0 = tid >> 2, q0 = tid & 3;

    // swizzle slot is identical for all 4 rows this thread stages (64 ≡ 0 mod 4
    // after >>1), so compute once:
    const int s0 = (q0 + (r0 >> 1)) & 3;

    // global source base for this thread's staging lane (row r0+Δ, quad q0)
    const float* gsrc = x + (size_t)(row0 + r0) * NCOLS + q0 * 4;
    const uint32_t xs_base = (uint32_t)__cvta_generic_to_shared(xs);
    // smem byte offset of (row r0+Δ, slot s0) within a buffer
    const uint32_t soff = (uint32_t)(r0 * XPAD + s0 * 4) * 4u;

    // ---- issue chunk 0 staging immediately ----
    {
        const uint32_t b = xs_base + soff;
        cp_async16(b,                      gsrc);
        cp_async16(b + 64 * XPAD * 4,      gsrc + (size_t)64  * NCOLS);
        cp_async16(b + 128 * XPAD * 4,     gsrc + (size_t)128 * NCOLS);
        cp_async16(b + 192 * XPAD * 4,     gsrc + (size_t)192 * NCOLS);
        cp_commit();
    }

    const float alpha = p_alpha[0];
    const float beta  = p_beta[0];
    const float a1  = p_a1[0];
    const float a2  = p_a2[0];
    const float a3  = p_a3[0];
    const float wa1 = p_wa1[0];
    const float wa2 = p_wa2[0];
    const float inv_a1  = 1.0f / a1;
    const float inv_a2  = 1.0f / a2;
    const float inv_a3  = 1.0f / a3;
    const float inv_wa1 = 1.0f / wa1;
    const float inv_wa2 = 1.0f / wa2;

    // ---- quantize + pack W1 (16x128) into smem, layout [kc][j] ----
    for (int i = tid; i < 512; i += THREADS) {
        const int kc = i >> 4, j = i & 15;
        unsigned v = 0;
#pragma unroll
        for (int b = 0; b < 4; ++b) {
            float t = W1[j * 128 + kc * 4 + b] * inv_wa1;
            int q;
            asm("cvt.rni.sat.s8.f32 %0, %1;" : "=r"(q) : "f"(t));
            v = __byte_perm(v, (unsigned)q, 0x4321);
        }
        w1p[i] = (int)v;
    }
    // ---- quantize + pack W2 (10x16), preload biases ----
    if (tid < 40) {
        const int j = tid >> 2, c = tid & 3;
        unsigned v = 0;
#pragma unroll
        for (int b = 0; b < 4; ++b) {
            float t = W2[j * 16 + c * 4 + b] * inv_wa2;
            int q;
            asm("cvt.rni.sat.s8.f32 %0, %1;" : "=r"(q) : "f"(t));
            v = __byte_perm(v, (unsigned)q, 0x4321);
        }
        w2p[tid] = (int)v;
    }
    if (tid >= 64 && tid < 80) b1s[tid - 64] = b1[tid - 64];
    if (tid >= 96 && tid < 106) b2s[tid - 96] = b2[tid - 96];
    // (ordered for all threads by the first pipeline __syncthreads)

    float w = 1.0f;
    int acc[16];
#pragma unroll
    for (int j = 0; j < 16; ++j) acc[j] = 0;
    unsigned hp = 0;

    const int half = tid >> 1;

#pragma unroll
    for (int c = 0; c < NCHUNK; ++c) {
        // issue staging for chunk c+1 into the other buffer.
        // safe: that buffer was last read by chunk c-1's compute, and every
        // thread passed the trailing barrier of iteration c-1.
        if (c < NCHUNK - 1) {
            const uint32_t b = xs_base + (((c + 1) & 1) ? BUFSZ * 4u : 0u) + soff;
            const float* g = gsrc + (c + 1) * 16;
            cp_async16(b,                  g);
            cp_async16(b + 64 * XPAD * 4,  g + (size_t)64  * NCOLS);
            cp_async16(b + 128 * XPAD * 4, g + (size_t)128 * NCOLS);
            cp_async16(b + 192 * XPAD * 4, g + (size_t)192 * NCOLS);
            cp_commit();
            cp_wait<1>();       // chunk c's group complete (c+1 may be in flight)
        } else {
            cp_wait<0>();
        }
        __syncthreads();        // make chunk c's data visible to all threads

        // 16 recurrence steps + 4 dp4a groups; one vector LDS per group
        const float* xr = &xs[(c & 1) * BUFSZ + tid * XPAD];
#pragma unroll
        for (int g = 0; g < 4; ++g) {
            const int s = (g + half) & 3;
            const float4 v = *reinterpret_cast<const float4*>(&xr[s * 4]);
            const float xe[4] = {v.x, v.y, v.z, v.w};
#pragma unroll
            for (int b = 0; b < 4; ++b) {
                // quantize w_k: clip+round-half-even == cvt.rni.sat.s8
                const float t = w * inv_a1;
                int hq;
                asm("cvt.rni.sat.s8.f32 %0, %1;" : "=r"(hq) : "f"(t));
                hp = __byte_perm(hp, (unsigned)hq, 0x4321);
                // w' = alpha*rcp(w) + (w - beta*x_k); t2 fma overlaps the MUFU
                const float t2 = __fmaf_rn(-beta, xe[b], w);
                float r;
                asm("rcp.approx.f32 %0, %1;" : "=f"(r) : "f"(w));
                w = __fmaf_rn(alpha, r, t2);
            }
            const int kc = c * 4 + g;
            const int4* wp = reinterpret_cast<const int4*>(&w1p[kc * 16]);
            const int4 w0 = wp[0], w1v = wp[1], w2v = wp[2], w3v = wp[3];
            acc[0]  = __dp4a((int)hp, w0.x,  acc[0]);
            acc[1]  = __dp4a((int)hp, w0.y,  acc[1]);
            acc[2]  = __dp4a((int)hp, w0.z,  acc[2]);
            acc[3]  = __dp4a((int)hp, w0.w,  acc[3]);
            acc[4]  = __dp4a((int)hp, w1v.x, acc[4]);
            acc[5]  = __dp4a((int)hp, w1v.y, acc[5]);
            acc[6]  = __dp4a((int)hp, w1v.z, acc[6]);
            acc[7]  = __dp4a((int)hp, w1v.w, acc[7]);
            acc[8]  = __dp4a((int)hp, w2v.x, acc[8]);
            acc[9]  = __dp4a((int)hp, w2v.y, acc[9]);
            acc[10] = __dp4a((int)hp, w2v.z, acc[10]);
            acc[11] = __dp4a((int)hp, w2v.w, acc[11]);
            acc[12] = __dp4a((int)hp, w3v.x, acc[12]);
            acc[13] = __dp4a((int)hp, w3v.y, acc[13]);
            acc[14] = __dp4a((int)hp, w3v.z, acc[14]);
            acc[15] = __dp4a((int)hp, w3v.w, acc[15]);
        }
        __syncthreads();        // compute(c) done before buffer gets re-staged
    }

    // ---- epilogue: bias, sigmoid, unsigned quant, signed quant, fc2 (dp4a) ----
    const float s1scale = a1 * wa1;
    unsigned sp[4];
    unsigned spacc = 0;
#pragma unroll
    for (int j = 0; j < 16; ++j) {
        const float h = __fmaf_rn((float)acc[j], s1scale, b1s[j]);
        const float sg = __fdividef(1.0f, 1.0f + __expf(-h));
        float u = sg * inv_a2;
        u = fminf(fmaxf(u, 0.0f), 255.0f);
        const float s = (float)__float2int_rn(u) * a2;          // post-sigmoid fq
        const float v2 = s * inv_a3;
        int s2q;
        asm("cvt.rni.sat.s8.f32 %0, %1;" : "=r"(s2q) : "f"(v2)); // qAct3 level
        spacc = __byte_perm(spacc, (unsigned)s2q, 0x4321);
        if ((j & 3) == 3) sp[j >> 2] = spacc;
    }

    // staging buffers idle after the last trailing barrier -> reuse
    float* outs = xs;
    const float s2scale = a3 * wa2;
#pragma unroll
    for (int j = 0; j < 10; ++j) {
        int o = 0;
        o = __dp4a((int)sp[0], w2p[j * 4 + 0], o);
        o = __dp4a((int)sp[1], w2p[j * 4 + 1], o);
        o = __dp4a((int)sp[2], w2p[j * 4 + 2], o);
        o = __dp4a((int)sp[3], w2p[j * 4 + 3], o);
        outs[tid * 10 + j] = __fmaf_rn((float)o, s2scale, b2s[j]);
    }
    __syncthreads();

    // coalesced output store: 2560 contiguous floats per block
    const size_t obase = (size_t)row0 * 10;
#pragma unroll
    for (int t = 0; t < 10; ++t) {
        const int i = t * THREADS + tid;
        out[obase + i] = outs[i];
    }
}

extern "C" void kernel_launch(void* const* d_in, const int* in_sizes, int n_in,
                              void* d_out, int out_size)
{
    const float* x       = (const float*)d_in[0];
    const float* p_alpha = (const float*)d_in[1];
    const float* p_beta  = (const float*)d_in[2];
    const float* p_a1    = (const float*)d_in[3];
    const float* p_a2    = (const float*)d_in[4];
    const float* p_a3    = (const float*)d_in[5];
    const float* W1      = (const float*)d_in[6];
    const float* b1      = (const float*)d_in[7];
    const float* p_wa1   = (const float*)d_in[8];
    const float* W2      = (const float*)d_in[9];
    const float* b2      = (const float*)d_in[10];
    const float* p_wa2   = (const float*)d_in[11];
    float* out = (float*)d_out;

    const int M = in_sizes[0] / NCOLS;     // 262144
    const int blocks = M / THREADS;        // 1024

    net_quant_kernel<<<blocks, THREADS>>>(x, p_alpha, p_beta, p_a1, p_a2, p_a3,
                                          W1, b1, p_wa1, W2, b2, p_wa2, out);
}